// round 3
// baseline (speedup 1.0000x reference)
#include <cuda_runtime.h>
#include <cuda_bf16.h>
#include <mma.h>

using namespace nvcuda;

#define BATCH  16384
#define DDIM   1024
#define HDIM   1024
#define KTOT   2048        // D + H (concatenated k)
#define BM 128             // batch rows per block
#define BN 64              // h columns per block
#define BK 32
#define LDS_LD 48          // padded smem leading dim for bf16 tiles

// Dynamic smem layout (bytes):
//   [0, 163840)            gates[5][BM][BN] fp32
//   [163840, +12288)       As_hi [BM][LDS_LD] bf16
//   [176128, +12288)       As_lo
//   [188416, +6144)        Bs_hi [BN][LDS_LD] bf16
//   [194560, +6144)        Bs_lo
#define GATES_BYTES (5 * BM * BN * 4)
#define A_BYTES     (BM * LDS_LD * 2)
#define B_BYTES     (BN * LDS_LD * 2)
#define SMEM_TOTAL  (GATES_BYTES + 2 * A_BYTES + 2 * B_BYTES)   // 200704

__device__ __forceinline__ float sigmoidf_fast(float v) {
    return 1.0f / (1.0f + __expf(-v));
}

__global__ __launch_bounds__(256, 1)
void lstm_fused_kernel(const float* __restrict__ x,
                       const float* __restrict__ h_prev,
                       const float* __restrict__ c_prev,
                       const float* __restrict__ dw,
                       const float* __restrict__ Wx,
                       const float* __restrict__ bx,
                       const float* __restrict__ Uh,
                       const float* __restrict__ bh,
                       float* __restrict__ out)
{
    extern __shared__ char smem_raw[];
    float (*gates)[BM][BN] = (float (*)[BM][BN])smem_raw;
    __nv_bfloat16 (*As_hi)[LDS_LD] = (__nv_bfloat16 (*)[LDS_LD])(smem_raw + GATES_BYTES);
    __nv_bfloat16 (*As_lo)[LDS_LD] = (__nv_bfloat16 (*)[LDS_LD])(smem_raw + GATES_BYTES + A_BYTES);
    __nv_bfloat16 (*Bs_hi)[LDS_LD] = (__nv_bfloat16 (*)[LDS_LD])(smem_raw + GATES_BYTES + 2 * A_BYTES);
    __nv_bfloat16 (*Bs_lo)[LDS_LD] = (__nv_bfloat16 (*)[LDS_LD])(smem_raw + GATES_BYTES + 2 * A_BYTES + B_BYTES);

    const int m0 = blockIdx.y * BM;   // batch offset
    const int h0 = blockIdx.x * BN;   // hidden-unit offset
    const int tid  = threadIdx.x;
    const int warp = tid >> 5;
    const int wm = (warp >> 1) * 32;  // warp m-offset: 0,32,64,96
    const int wn = (warp & 1) * 32;   // warp n-offset: 0,32

    // Loader mapping: one tile row of 32 floats = 8 float4.
    const int f4c   = tid & 7;        // float4 column in row
    const int rbase = tid >> 3;       // row 0..31, strided by 32

    for (int g = 0; g < 5; g++) {
        wmma::fragment<wmma::accumulator, 16, 16, 16, float> acc[2][2];
        #pragma unroll
        for (int i = 0; i < 2; i++)
            #pragma unroll
            for (int j = 0; j < 2; j++)
                wmma::fill_fragment(acc[i][j], 0.0f);

        for (int k0 = 0; k0 < KTOT; k0 += BK) {
            const float* Asrc;
            const float* Bsrc;
            int kk;
            if (k0 < DDIM) { Asrc = x;      Bsrc = Wx; kk = k0; }
            else           { Asrc = h_prev; Bsrc = Uh; kk = k0 - DDIM; }

            __syncthreads();
            // A tile: 128 rows
            #pragma unroll
            for (int q = 0; q < 4; q++) {
                int r = rbase + 32 * q;
                int c = f4c * 4;
                float4 av = *(const float4*)(&Asrc[(size_t)(m0 + r) * 1024 + kk + c]);
                float a[4] = {av.x, av.y, av.z, av.w};
                #pragma unroll
                for (int u = 0; u < 4; u++) {
                    __nv_bfloat16 ah = __float2bfloat16(a[u]);
                    As_hi[r][c + u] = ah;
                    As_lo[r][c + u] = __float2bfloat16(a[u] - __bfloat162float(ah));
                }
            }
            // B tile: 64 rows of gate g's weight band
            #pragma unroll
            for (int q = 0; q < 2; q++) {
                int r = rbase + 32 * q;
                int c = f4c * 4;
                float4 bv = *(const float4*)(&Bsrc[(size_t)((g << 10) + h0 + r) * 1024 + kk + c]);
                float b[4] = {bv.x, bv.y, bv.z, bv.w};
                #pragma unroll
                for (int u = 0; u < 4; u++) {
                    __nv_bfloat16 bhv = __float2bfloat16(b[u]);
                    Bs_hi[r][c + u] = bhv;
                    Bs_lo[r][c + u] = __float2bfloat16(b[u] - __bfloat162float(bhv));
                }
            }
            __syncthreads();

            #pragma unroll
            for (int ks = 0; ks < BK; ks += 16) {
                wmma::fragment<wmma::matrix_b, 16, 16, 16, __nv_bfloat16, wmma::col_major> bhf[2], blf[2];
                #pragma unroll
                for (int j = 0; j < 2; j++) {
                    wmma::load_matrix_sync(bhf[j], &Bs_hi[wn + j * 16][ks], LDS_LD);
                    wmma::load_matrix_sync(blf[j], &Bs_lo[wn + j * 16][ks], LDS_LD);
                }
                #pragma unroll
                for (int i = 0; i < 2; i++) {
                    wmma::fragment<wmma::matrix_a, 16, 16, 16, __nv_bfloat16, wmma::row_major> ahf, alf;
                    wmma::load_matrix_sync(ahf, &As_hi[wm + i * 16][ks], LDS_LD);
                    wmma::load_matrix_sync(alf, &As_lo[wm + i * 16][ks], LDS_LD);
                    #pragma unroll
                    for (int j = 0; j < 2; j++) {
                        wmma::mma_sync(acc[i][j], ahf, bhf[j], acc[i][j]);  // hi*hi
                        wmma::mma_sync(acc[i][j], ahf, blf[j], acc[i][j]);  // hi*lo
                        wmma::mma_sync(acc[i][j], alf, bhf[j], acc[i][j]);  // lo*hi
                    }
                }
            }
        }

        // Stage this gate's pre-activations in smem.
        #pragma unroll
        for (int i = 0; i < 2; i++)
            #pragma unroll
            for (int j = 0; j < 2; j++)
                wmma::store_matrix_sync(&gates[g][wm + i * 16][wn + j * 16], acc[i][j],
                                        BN, wmma::mem_row_major);
    }

    // All gate GEMMs done; tiles no longer needed.
    __syncthreads();

    // Cache bias sums for this h-band: bsum[g][c] = bx[g*1024+h0+c] + bh[...]
    float* bsum = (float*)(smem_raw + GATES_BYTES);   // reuse tile space (5*64*4 = 1280 B)
    for (int i = tid; i < 5 * BN; i += 256) {
        int gg = i / BN, cc = i % BN;
        int gidx = (gg << 10) + h0 + cc;
        bsum[i] = bx[gidx] + bh[gidx];
    }
    __syncthreads();

    // Epilogue: 128*64 = 8192 elements, 32 per thread, coalesced.
    #pragma unroll
    for (int e = 0; e < 32; e++) {
        int lin = e * 256 + tid;
        int r = lin >> 6;          // 0..127
        int c = lin & 63;          // 0..63
        int b = m0 + r;
        int h = h0 + c;
        size_t idx = (size_t)b * 1024 + h;

        float gi = gates[0][r][c] + bsum[0 * BN + c];
        float gf = gates[1][r][c] + bsum[1 * BN + c];
        float go = gates[2][r][c] + bsum[2 * BN + c];
        float gc = gates[3][r][c] + bsum[3 * BN + c];
        float gs = gates[4][r][c] + bsum[4 * BN + c];

        float i_t   = sigmoidf_fast(gi);
        float f_t   = sigmoidf_fast(gf);
        float o_t   = sigmoidf_fast(go);
        float c_hat = tanhf(gc);
        float s_t   = sigmoidf_fast(gs) * dw[idx];

        float c_t = f_t * c_prev[idx] + i_t * c_hat * s_t;
        float h_t = o_t * tanhf(c_t);

        out[idx] = h_t;
        out[(size_t)BATCH * HDIM + idx] = c_t;
    }
}

// ---------------------------------------------------------------------------
// Inputs (metadata order): x, h_prev, c_prev, dynamic_weight, Wx, bx, Uh, bh
// ---------------------------------------------------------------------------
extern "C" void kernel_launch(void* const* d_in, const int* in_sizes, int n_in,
                              void* d_out, int out_size)
{
    const float* x  = (const float*)d_in[0];
    const float* hp = (const float*)d_in[1];
    const float* cp = (const float*)d_in[2];
    const float* dw = (const float*)d_in[3];
    const float* Wx = (const float*)d_in[4];
    const float* bx = (const float*)d_in[5];
    const float* Uh = (const float*)d_in[6];
    const float* bh = (const float*)d_in[7];
    float* out = (float*)d_out;

    cudaFuncSetAttribute(lstm_fused_kernel,
                         cudaFuncAttributeMaxDynamicSharedMemorySize, SMEM_TOTAL);

    dim3 grid(HDIM / BN, BATCH / BM);   // (16, 128)
    lstm_fused_kernel<<<grid, 256, SMEM_TOTAL>>>(x, hp, cp, dw, Wx, bx, Uh, bh, out);
}

// round 5
// speedup vs baseline: 1.6160x; 1.6160x over previous
#include <cuda_runtime.h>
#include <cuda_bf16.h>
#include <mma.h>
#include <cstdint>

using namespace nvcuda;

#define BATCH  16384
#define HDIM   1024
#define KTOT   2048
#define BM     64            // batch rows per CTA
#define HB     32            // h columns per CTA
#define NG     160           // 5 gates * HB accumulator columns
#define BK     32            // K per chunk
#define NCHUNK (KTOT / BK)   // 64
#define LDSLD  48            // smem leading dim (bf16 elements)

// Stage layout (bytes)
#define A_BYTES (BM * LDSLD * 2)     // 6144
#define B_BYTES (NG * LDSLD * 2)     // 15360
#define A_HI 0
#define A_LO (A_BYTES)
#define B_HI (2 * A_BYTES)
#define B_LO (2 * A_BYTES + B_BYTES)
#define STAGE (2 * A_BYTES + 2 * B_BYTES)   // 43008
#define GLD  164                             // gates smem row stride (floats)
#define BSUM_OFF (2 * STAGE)                 // 86016
#define SMEM_REQ (BSUM_OFF + 1024)           // 87040

// fp32 -> packed bf16 hi pair + bf16 residual-lo pair
__device__ __forceinline__ void cvt_pair(float a, float b, uint32_t& hi, uint32_t& lo) {
    uint32_t h;
    asm("cvt.rn.bf16x2.f32 %0, %1, %2;" : "=r"(h) : "f"(b), "f"(a));   // lo16=a, hi16=b
    float ra_ = a - __uint_as_float(h << 16);
    float rb_ = b - __uint_as_float(h & 0xFFFF0000u);
    asm("cvt.rn.bf16x2.f32 %0, %1, %2;" : "=r"(lo) : "f"(rb_), "f"(ra_));
    hi = h;
}
__device__ __forceinline__ float sigmoidf_fast(float v) { return 1.0f / (1.0f + __expf(-v)); }

__global__ __launch_bounds__(256, 2)
void lstm_mma_kernel(const float* __restrict__ x, const float* __restrict__ h_prev,
                     const float* __restrict__ c_prev, const float* __restrict__ dw,
                     const float* __restrict__ Wx, const float* __restrict__ bx,
                     const float* __restrict__ Uh, const float* __restrict__ bh,
                     float* __restrict__ out)
{
    extern __shared__ char sm[];
    const int tid  = threadIdx.x;
    const int warp = tid >> 5;
    const int m0 = blockIdx.y * BM;
    const int h0 = blockIdx.x * HB;

    // Warp grid: 4 (m) x 2 (n). Warp tile: 16(m) x 80(n) -> 5 acc frags.
    const int wm = (warp & 3) * 16;
    const int wn = (warp >> 2) * 80;

    wmma::fragment<wmma::accumulator, 16, 16, 16, float> acc[5];
    #pragma unroll
    for (int j = 0; j < 5; j++) wmma::fill_fragment(acc[j], 0.0f);

    // Loader mapping: one "unit" = 8 consecutive fp32 (2 float4) of one row.
    // A: 64 rows x 4 units = 256 units (1/thread). B: 160 x 4 = 640 units.
    const int arow = tid >> 2, aseg = tid & 3;

    float4 a0, a1, b0[3], b1[3];

    auto ldg_chunk = [&](int c) {
        const float* As; const float* Bs; int kk;
        if (c < NCHUNK / 2) { As = x;      Bs = Wx; kk = c * BK; }
        else                { As = h_prev; Bs = Uh; kk = c * BK - 1024; }
        {
            const float* g = As + (size_t)(m0 + arow) * 1024 + kk + aseg * 8;
            a0 = *(const float4*)g;  a1 = *(const float4*)(g + 4);
        }
        #pragma unroll
        for (int p = 0; p < 3; p++) {
            int u = tid + p * 256;
            if (p < 2 || tid < 128) {
                int row = u >> 2, seg = u & 3;          // row 0..159
                int gg = row >> 5, hr = row & 31;
                const float* g = Bs + (size_t)(gg * 1024 + h0 + hr) * 1024 + kk + seg * 8;
                b0[p] = *(const float4*)g;  b1[p] = *(const float4*)(g + 4);
            }
        }
    };
    auto sts_chunk = [&](int s) {
        char* base = sm + s * STAGE;
        {
            uint4 hi, lo;
            cvt_pair(a0.x, a0.y, hi.x, lo.x);  cvt_pair(a0.z, a0.w, hi.y, lo.y);
            cvt_pair(a1.x, a1.y, hi.z, lo.z);  cvt_pair(a1.z, a1.w, hi.w, lo.w);
            uint32_t off = arow * (LDSLD * 2) + aseg * 16;
            *(uint4*)(base + A_HI + off) = hi;
            *(uint4*)(base + A_LO + off) = lo;
        }
        #pragma unroll
        for (int p = 0; p < 3; p++) {
            int u = tid + p * 256;
            if (p < 2 || tid < 128) {
                int row = u >> 2, seg = u & 3;
                uint4 hi, lo;
                cvt_pair(b0[p].x, b0[p].y, hi.x, lo.x);  cvt_pair(b0[p].z, b0[p].w, hi.y, lo.y);
                cvt_pair(b1[p].x, b1[p].y, hi.z, lo.z);  cvt_pair(b1[p].z, b1[p].w, hi.w, lo.w);
                uint32_t off = row * (LDSLD * 2) + seg * 16;
                *(uint4*)(base + B_HI + off) = hi;
                *(uint4*)(base + B_LO + off) = lo;
            }
        }
    };

    // ---- prologue: chunk 0 -------------------------------------------------
    ldg_chunk(0);
    sts_chunk(0);
    __syncthreads();

    // ---- pipelined main loop ----------------------------------------------
    for (int i = 0; i < NCHUNK; i++) {
        const int s = i & 1;
        if (i + 1 < NCHUNK) ldg_chunk(i + 1);   // LDGs in flight during mma

        const __nv_bfloat16* Ah = (const __nv_bfloat16*)(sm + s * STAGE + A_HI);
        const __nv_bfloat16* Al = (const __nv_bfloat16*)(sm + s * STAGE + A_LO);
        const __nv_bfloat16* Bh = (const __nv_bfloat16*)(sm + s * STAGE + B_HI);
        const __nv_bfloat16* Bl = (const __nv_bfloat16*)(sm + s * STAGE + B_LO);

        #pragma unroll
        for (int ks = 0; ks < BK; ks += 16) {
            wmma::fragment<wmma::matrix_a, 16, 16, 16, __nv_bfloat16, wmma::row_major> ahf, alf;
            wmma::load_matrix_sync(ahf, Ah + wm * LDSLD + ks, LDSLD);
            wmma::load_matrix_sync(alf, Al + wm * LDSLD + ks, LDSLD);
            #pragma unroll
            for (int j = 0; j < 5; j++) {
                wmma::fragment<wmma::matrix_b, 16, 16, 16, __nv_bfloat16, wmma::col_major> bhf, blf;
                wmma::load_matrix_sync(bhf, Bh + (wn + j * 16) * LDSLD + ks, LDSLD);
                wmma::load_matrix_sync(blf, Bl + (wn + j * 16) * LDSLD + ks, LDSLD);
                wmma::mma_sync(acc[j], ahf, bhf, acc[j]);   // hi*hi
                wmma::mma_sync(acc[j], ahf, blf, acc[j]);   // hi*lo
                wmma::mma_sync(acc[j], alf, bhf, acc[j]);   // lo*hi
            }
        }
        __syncthreads();
        if (i + 1 < NCHUNK) {
            sts_chunk(s ^ 1);
            __syncthreads();
        }
    }

    // ---- stage gates in smem (reuses stage-0 region) -----------------------
    float* gates = (float*)sm;                    // [64][GLD]
    float* bsum  = (float*)(sm + BSUM_OFF);       // [160]
    #pragma unroll
    for (int j = 0; j < 5; j++)
        wmma::store_matrix_sync(gates + wm * GLD + wn + j * 16, acc[j],
                                GLD, wmma::mem_row_major);
    if (tid < NG) {
        int g = tid >> 5, c = tid & 31;
        int gi = g * 1024 + h0 + c;
        bsum[tid] = bx[gi] + bh[gi];
    }
    __syncthreads();

    // ---- fused LSTM epilogue ----------------------------------------------
    #pragma unroll
    for (int p = 0; p < 8; p++) {
        int r = (tid >> 5) + p * 8;      // 0..63
        int c = tid & 31;                // 0..31
        size_t gidx = (size_t)(m0 + r) * 1024 + h0 + c;
        const float* gr = gates + r * GLD;

        float gi_ = gr[c]            + bsum[c];
        float gf_ = gr[32 + c]       + bsum[32 + c];
        float go_ = gr[64 + c]       + bsum[64 + c];
        float gc_ = gr[96 + c]       + bsum[96 + c];
        float gs_ = gr[128 + c]      + bsum[128 + c];

        float i_t   = sigmoidf_fast(gi_);
        float f_t   = sigmoidf_fast(gf_);
        float o_t   = sigmoidf_fast(go_);
        float c_hat = tanhf(gc_);
        float s_t   = sigmoidf_fast(gs_) * dw[gidx];

        float c_t = f_t * c_prev[gidx] + i_t * c_hat * s_t;
        float h_t = o_t * tanhf(c_t);

        out[gidx] = h_t;
        out[(size_t)BATCH * HDIM + gidx] = c_t;
    }
}

// ---------------------------------------------------------------------------
// Inputs (metadata order): x, h_prev, c_prev, dynamic_weight, Wx, bx, Uh, bh
// ---------------------------------------------------------------------------
extern "C" void kernel_launch(void* const* d_in, const int* in_sizes, int n_in,
                              void* d_out, int out_size)
{
    const float* x  = (const float*)d_in[0];
    const float* hp = (const float*)d_in[1];
    const float* cp = (const float*)d_in[2];
    const float* dw = (const float*)d_in[3];
    const float* Wx = (const float*)d_in[4];
    const float* bx = (const float*)d_in[5];
    const float* Uh = (const float*)d_in[6];
    const float* bh = (const float*)d_in[7];
    float* out = (float*)d_out;

    cudaFuncSetAttribute(lstm_mma_kernel,
                         cudaFuncAttributeMaxDynamicSharedMemorySize, SMEM_REQ);

    dim3 grid(HDIM / HB, BATCH / BM);   // (32, 256)
    lstm_mma_kernel<<<grid, 256, SMEM_REQ>>>(x, hp, cp, dw, Wx, bx, Uh, bh, out);
}

// round 9
// speedup vs baseline: 1.6853x; 1.0428x over previous
#include <cuda_runtime.h>
#include <cuda_bf16.h>
#include <mma.h>
#include <cstdint>

using namespace nvcuda;

#define BATCH  16384
#define HDIM   1024
#define KTOT   2048
#define BM     128           // batch rows per CTA
#define HB     32            // h columns per CTA
#define NG     160           // 5 gates * HB accumulator columns
#define BK     32            // K per chunk
#define NCHUNK (KTOT / BK)   // 64
#define LDSLD  40            // smem leading dim (bf16): 80B pitch, conflict-free LDSM

// Stage layout (bytes)
#define A_BYTES (BM * LDSLD * 2)     // 10240
#define B_BYTES (NG * LDSLD * 2)     // 12800
#define A_HI 0
#define A_LO (A_BYTES)
#define B_HI (2 * A_BYTES)
#define B_LO (2 * A_BYTES + B_BYTES)
#define STAGE (2 * A_BYTES + 2 * B_BYTES)   // 46080
#define GLD  164                             // gates smem row stride (floats)
#define BSUM_OFF (STAGE * 2)                 // 92160 (gates reuse: 128*164*4 = 83968 < 92160)
#define SMEM_REQ (BSUM_OFF + 1024)           // 93184

// fp32 -> packed bf16 hi pair + bf16 residual-lo pair
__device__ __forceinline__ void cvt_pair(float a, float b, uint32_t& hi, uint32_t& lo) {
    uint32_t h;
    asm("cvt.rn.bf16x2.f32 %0, %1, %2;" : "=r"(h) : "f"(b), "f"(a));   // lo16=a, hi16=b
    float ra_ = a - __uint_as_float(h << 16);
    float rb_ = b - __uint_as_float(h & 0xFFFF0000u);
    asm("cvt.rn.bf16x2.f32 %0, %1, %2;" : "=r"(lo) : "f"(rb_), "f"(ra_));
    hi = h;
}
__device__ __forceinline__ float sigmoidf_fast(float v) { return 1.0f / (1.0f + __expf(-v)); }

__global__ __launch_bounds__(256, 1)
void lstm_mma_kernel(const float* __restrict__ x, const float* __restrict__ h_prev,
                     const float* __restrict__ c_prev, const float* __restrict__ dw,
                     const float* __restrict__ Wx, const float* __restrict__ bx,
                     const float* __restrict__ Uh, const float* __restrict__ bh,
                     float* __restrict__ out)
{
    extern __shared__ char sm[];
    const int tid  = threadIdx.x;
    const int warp = tid >> 5;
    const int m0 = blockIdx.y * BM;
    const int h0 = blockIdx.x * HB;

    // Warp grid: 4 (m) x 2 (n). Warp tile: 32(m) x 80(n) -> acc[2][5].
    const int wm = (warp & 3) * 32;
    const int wn = (warp >> 2) * 80;

    wmma::fragment<wmma::accumulator, 16, 16, 16, float> acc[2][5];
    #pragma unroll
    for (int i = 0; i < 2; i++)
        #pragma unroll
        for (int j = 0; j < 5; j++) wmma::fill_fragment(acc[i][j], 0.0f);

    // Loader: one unit = 8 consecutive fp32 (2 float4) of one row.
    // A: 128 rows x 4 units = 512 (2/thread).  B: 160 x 4 = 640 (2.5/thread).
    float4 a0[2], a1[2], b0[3], b1[3];

    auto ldg_chunk = [&](int c) {
        const float* As; const float* Bs; int kk;
        if (c < NCHUNK / 2) { As = x;      Bs = Wx; kk = c * BK; }
        else                { As = h_prev; Bs = Uh; kk = c * BK - 1024; }
        #pragma unroll
        for (int p = 0; p < 2; p++) {
            int u = tid + p * 256;
            int row = u >> 2, seg = u & 3;
            const float* g = As + (size_t)(m0 + row) * 1024 + kk + seg * 8;
            a0[p] = *(const float4*)g;  a1[p] = *(const float4*)(g + 4);
        }
        #pragma unroll
        for (int p = 0; p < 3; p++) {
            if (p < 2 || tid < 128) {
                int u = tid + p * 256;
                int row = u >> 2, seg = u & 3;          // row 0..159
                int gg = row >> 5, hr = row & 31;
                const float* g = Bs + (size_t)(gg * 1024 + h0 + hr) * 1024 + kk + seg * 8;
                b0[p] = *(const float4*)g;  b1[p] = *(const float4*)(g + 4);
            }
        }
    };
    auto sts_chunk = [&](int s) {
        char* base = sm + s * STAGE;
        #pragma unroll
        for (int p = 0; p < 2; p++) {
            int u = tid + p * 256;
            int row = u >> 2, seg = u & 3;
            uint4 hi, lo;
            cvt_pair(a0[p].x, a0[p].y, hi.x, lo.x);  cvt_pair(a0[p].z, a0[p].w, hi.y, lo.y);
            cvt_pair(a1[p].x, a1[p].y, hi.z, lo.z);  cvt_pair(a1[p].z, a1[p].w, hi.w, lo.w);
            uint32_t off = row * (LDSLD * 2) + seg * 16;
            *(uint4*)(base + A_HI + off) = hi;
            *(uint4*)(base + A_LO + off) = lo;
        }
        #pragma unroll
        for (int p = 0; p < 3; p++) {
            if (p < 2 || tid < 128) {
                int u = tid + p * 256;
                int row = u >> 2, seg = u & 3;
                uint4 hi, lo;
                cvt_pair(b0[p].x, b0[p].y, hi.x, lo.x);  cvt_pair(b0[p].z, b0[p].w, hi.y, lo.y);
                cvt_pair(b1[p].x, b1[p].y, hi.z, lo.z);  cvt_pair(b1[p].z, b1[p].w, hi.w, lo.w);
                uint32_t off = row * (LDSLD * 2) + seg * 16;
                *(uint4*)(base + B_HI + off) = hi;
                *(uint4*)(base + B_LO + off) = lo;
            }
        }
    };

    // ---- prologue ----------------------------------------------------------
    ldg_chunk(0);
    sts_chunk(0);
    __syncthreads();

    // ---- pipelined main loop ----------------------------------------------
    for (int i = 0; i < NCHUNK; i++) {
        const int s = i & 1;
        if (i + 1 < NCHUNK) ldg_chunk(i + 1);   // LDGs in flight during mma

        const __nv_bfloat16* Ah = (const __nv_bfloat16*)(sm + s * STAGE + A_HI);
        const __nv_bfloat16* Al = (const __nv_bfloat16*)(sm + s * STAGE + A_LO);
        const __nv_bfloat16* Bh = (const __nv_bfloat16*)(sm + s * STAGE + B_HI);
        const __nv_bfloat16* Bl = (const __nv_bfloat16*)(sm + s * STAGE + B_LO);

        #pragma unroll
        for (int ks = 0; ks < BK; ks += 16) {
            wmma::fragment<wmma::matrix_a, 16, 16, 16, __nv_bfloat16, wmma::row_major> ahf[2], alf[2];
            #pragma unroll
            for (int i2 = 0; i2 < 2; i2++) {
                wmma::load_matrix_sync(ahf[i2], Ah + (wm + i2 * 16) * LDSLD + ks, LDSLD);
                wmma::load_matrix_sync(alf[i2], Al + (wm + i2 * 16) * LDSLD + ks, LDSLD);
            }
            #pragma unroll
            for (int j = 0; j < 5; j++) {
                wmma::fragment<wmma::matrix_b, 16, 16, 16, __nv_bfloat16, wmma::col_major> bhf, blf;
                wmma::load_matrix_sync(bhf, Bh + (wn + j * 16) * LDSLD + ks, LDSLD);
                wmma::load_matrix_sync(blf, Bl + (wn + j * 16) * LDSLD + ks, LDSLD);
                #pragma unroll
                for (int i2 = 0; i2 < 2; i2++) {
                    wmma::mma_sync(acc[i2][j], ahf[i2], bhf, acc[i2][j]);   // hi*hi
                    wmma::mma_sync(acc[i2][j], ahf[i2], blf, acc[i2][j]);   // hi*lo
                    wmma::mma_sync(acc[i2][j], alf[i2], bhf, acc[i2][j]);   // lo*hi
                }
            }
        }
        __syncthreads();
        if (i + 1 < NCHUNK) {
            sts_chunk(s ^ 1);
            __syncthreads();
        }
    }

    // ---- stage gates in smem (reuses stage region) -------------------------
    float* gates = (float*)sm;                    // [128][GLD]
    float* bsum  = (float*)(sm + BSUM_OFF);       // [160]
    #pragma unroll
    for (int i2 = 0; i2 < 2; i2++)
        #pragma unroll
        for (int j = 0; j < 5; j++)
            wmma::store_matrix_sync(gates + (wm + i2 * 16) * GLD + wn + j * 16, acc[i2][j],
                                    GLD, wmma::mem_row_major);
    if (tid < NG) {
        int g = tid >> 5, c = tid & 31;
        int gi = g * 1024 + h0 + c;
        bsum[tid] = bx[gi] + bh[gi];
    }
    __syncthreads();

    // ---- fused LSTM epilogue: 128*32 elems, 16/thread ----------------------
    #pragma unroll
    for (int p = 0; p < 16; p++) {
        int r = (tid >> 5) + p * 8;      // 0..127
        int c = tid & 31;                // 0..31
        size_t gidx = (size_t)(m0 + r) * 1024 + h0 + c;
        const float* gr = gates + r * GLD;

        float gi_ = gr[c]       + bsum[c];
        float gf_ = gr[32 + c]  + bsum[32 + c];
        float go_ = gr[64 + c]  + bsum[64 + c];
        float gc_ = gr[96 + c]  + bsum[96 + c];
        float gs_ = gr[128 + c] + bsum[128 + c];

        float i_t   = sigmoidf_fast(gi_);
        float f_t   = sigmoidf_fast(gf_);
        float o_t   = sigmoidf_fast(go_);
        float c_hat = tanhf(gc_);
        float s_t   = sigmoidf_fast(gs_) * dw[gidx];

        float c_t = f_t * c_prev[gidx] + i_t * c_hat * s_t;
        float h_t = o_t * tanhf(c_t);

        out[gidx] = h_t;
        out[(size_t)BATCH * HDIM + gidx] = c_t;
    }
}

// ---------------------------------------------------------------------------
// Inputs (metadata order): x, h_prev, c_prev, dynamic_weight, Wx, bx, Uh, bh
// ---------------------------------------------------------------------------
extern "C" void kernel_launch(void* const* d_in, const int* in_sizes, int n_in,
                              void* d_out, int out_size)
{
    const float* x  = (const float*)d_in[0];
    const float* hp = (const float*)d_in[1];
    const float* cp = (const float*)d_in[2];
    const float* dw = (const float*)d_in[3];
    const float* Wx = (const float*)d_in[4];
    const float* bx = (const float*)d_in[5];
    const float* Uh = (const float*)d_in[6];
    const float* bh = (const float*)d_in[7];
    float* out = (float*)d_out;

    cudaFuncSetAttribute(lstm_mma_kernel,
                         cudaFuncAttributeMaxDynamicSharedMemorySize, SMEM_REQ);

    dim3 grid(HDIM / HB, BATCH / BM);   // (32, 128)
    lstm_mma_kernel<<<grid, 256, SMEM_REQ>>>(x, hp, cp, dw, Wx, bx, Uh, bh, out);
}

// round 10
// speedup vs baseline: 2.0560x; 1.2200x over previous
#include <cuda_runtime.h>
#include <cuda_bf16.h>
#include <mma.h>
#include <cstdint>

using namespace nvcuda;

#define BATCH  16384
#define HDIM   1024
#define KTOT   2048
#define WROWS  5120          // 5 gates * 1024
#define BM     128           // batch rows per CTA
#define HB     32            // h columns per CTA
#define NG     160           // 5 gates * HB
#define BK     32            // K per chunk
#define NCHUNK (KTOT / BK)   // 64
#define LDSLD  40            // 80B pitch, conflict-free LDSM
#define NSTAGE 4

// Stage layout (bytes)
#define A_HI 0
#define A_LO 10240           // 128*80
#define B_HI 20480
#define B_LO 33280           // +160*80
#define STAGE 46080
#define GLD  164             // gates smem row stride (floats)
#define BSUM_OFF (NSTAGE * STAGE)        // 184320 (gates reuse: 128*164*4=83968 fits below)
#define SMEM_REQ (BSUM_OFF + 1024)       // 185344

// Preprocessed bf16 hi/lo operands (static device scratch, 168 MB)
__device__ __nv_bfloat16 g_Ahi[(size_t)BATCH * KTOT];
__device__ __nv_bfloat16 g_Alo[(size_t)BATCH * KTOT];
__device__ __nv_bfloat16 g_Whi[(size_t)WROWS * KTOT];
__device__ __nv_bfloat16 g_Wlo[(size_t)WROWS * KTOT];

// fp32 pair -> packed bf16 hi pair + bf16 residual-lo pair
__device__ __forceinline__ void cvt_pair(float a, float b, uint32_t& hi, uint32_t& lo) {
    uint32_t h;
    asm("cvt.rn.bf16x2.f32 %0, %1, %2;" : "=r"(h) : "f"(b), "f"(a));   // lo16=a, hi16=b
    float ra_ = a - __uint_as_float(h << 16);
    float rb_ = b - __uint_as_float(h & 0xFFFF0000u);
    asm("cvt.rn.bf16x2.f32 %0, %1, %2;" : "=r"(lo) : "f"(rb_), "f"(ra_));
    hi = h;
}
__device__ __forceinline__ float sigmoidf_fast(float v) { return 1.0f / (1.0f + __expf(-v)); }

__device__ __forceinline__ uint32_t smem_u32(const void* p) {
    uint32_t a;
    asm("{ .reg .u64 t; cvta.to.shared.u64 t, %1; cvt.u32.u64 %0, t; }" : "=r"(a) : "l"(p));
    return a;
}
__device__ __forceinline__ void cpasync16(uint32_t dst, const void* src) {
    asm volatile("cp.async.cg.shared.global [%0], [%1], 16;" :: "r"(dst), "l"(src));
}
__device__ __forceinline__ void cp_commit() {
    asm volatile("cp.async.commit_group;" ::: "memory");
}
__device__ __forceinline__ void cp_wait2() {
    asm volatile("cp.async.wait_group 2;" ::: "memory");
}

// ---------------------------------------------------------------------------
// Preprocess: fp32 inputs -> bf16 hi/lo split arrays.
//   A[16384][2048] = [x | h_prev],  W[5120][2048] = [Wx | Uh]
// ---------------------------------------------------------------------------
__global__ __launch_bounds__(256)
void preprocess_kernel(const float* __restrict__ x, const float* __restrict__ h,
                       const float* __restrict__ Wx, const float* __restrict__ Uh)
{
    const size_t A_UNITS = (size_t)BATCH * KTOT / 8;   // 4194304
    const size_t W_UNITS = (size_t)WROWS * KTOT / 8;   // 1310720
    size_t u = (size_t)blockIdx.x * 256 + threadIdx.x;
    if (u >= A_UNITS + W_UNITS) return;

    const float* src;
    __nv_bfloat16 *dhi, *dlo;
    if (u < A_UNITS) {
        size_t row = u >> 8, col = (u & 255) * 8;
        src = (col < 1024) ? x + row * 1024 + col : h + row * 1024 + (col - 1024);
        dhi = g_Ahi + row * KTOT + col;
        dlo = g_Alo + row * KTOT + col;
    } else {
        size_t v = u - A_UNITS;
        size_t row = v >> 8, col = (v & 255) * 8;
        src = (col < 1024) ? Wx + row * 1024 + col : Uh + row * 1024 + (col - 1024);
        dhi = g_Whi + row * KTOT + col;
        dlo = g_Wlo + row * KTOT + col;
    }
    float4 f0 = *(const float4*)src;
    float4 f1 = *(const float4*)(src + 4);
    uint4 hi, lo;
    cvt_pair(f0.x, f0.y, hi.x, lo.x);
    cvt_pair(f0.z, f0.w, hi.y, lo.y);
    cvt_pair(f1.x, f1.y, hi.z, lo.z);
    cvt_pair(f1.z, f1.w, hi.w, lo.w);
    *(uint4*)dhi = hi;
    *(uint4*)dlo = lo;
}

// ---------------------------------------------------------------------------
// GEMM + fused LSTM epilogue. cp.async 4-stage pipeline, wmma 3-term split.
// ---------------------------------------------------------------------------
__global__ __launch_bounds__(256, 1)
void lstm_mma_kernel(const float* __restrict__ c_prev, const float* __restrict__ dw,
                     const float* __restrict__ bx, const float* __restrict__ bh,
                     float* __restrict__ out)
{
    extern __shared__ char sm[];
    const int tid  = threadIdx.x;
    const int warp = tid >> 5;
    const int m0 = blockIdx.y * BM;
    const int h0 = blockIdx.x * HB;
    const uint32_t smb = smem_u32(sm);

    // Warp grid 4(m) x 2(n); warp tile 32 x 80 -> acc[2][5].
    const int wm = (warp & 3) * 32;
    const int wn = (warp >> 2) * 80;

    wmma::fragment<wmma::accumulator, 16, 16, 16, float> acc[2][5];
    #pragma unroll
    for (int i = 0; i < 2; i++)
        #pragma unroll
        for (int j = 0; j < 5; j++) wmma::fill_fragment(acc[i][j], 0.0f);

    auto issue_stage = [&](int c) {
        const int kk = c * BK;
        const uint32_t base = smb + (c & (NSTAGE - 1)) * STAGE;
        #pragma unroll
        for (int p = 0; p < 2; p++) {
            int uu = tid + p * 256;
            int row = uu >> 2, seg = uu & 3;
            size_t go = (size_t)(m0 + row) * KTOT + kk + seg * 8;
            uint32_t d = base + row * 80 + seg * 16;
            cpasync16(d + A_HI, g_Ahi + go);
            cpasync16(d + A_LO, g_Alo + go);
        }
        #pragma unroll
        for (int p = 0; p < 3; p++) {
            if (p < 2 || tid < 128) {
                int uu = tid + p * 256;
                int row = uu >> 2, seg = uu & 3;          // 0..159
                int wr = (row >> 5) * 1024 + h0 + (row & 31);
                size_t go = (size_t)wr * KTOT + kk + seg * 8;
                uint32_t d = base + row * 80 + seg * 16;
                cpasync16(d + B_HI, g_Whi + go);
                cpasync16(d + B_LO, g_Wlo + go);
            }
        }
    };

    // Prologue: stages 0..2 in flight.
    #pragma unroll
    for (int c = 0; c < 3; c++) { issue_stage(c); cp_commit(); }

    // Main loop: one barrier per chunk; cp.async replaces the STS phase.
    for (int i = 0; i < NCHUNK; i++) {
        cp_wait2();            // stage i landed
        __syncthreads();

        const char* st = sm + (i & (NSTAGE - 1)) * STAGE;
        const __nv_bfloat16* Ah = (const __nv_bfloat16*)(st + A_HI);
        const __nv_bfloat16* Al = (const __nv_bfloat16*)(st + A_LO);
        const __nv_bfloat16* Bh = (const __nv_bfloat16*)(st + B_HI);
        const __nv_bfloat16* Bl = (const __nv_bfloat16*)(st + B_LO);

        #pragma unroll
        for (int ks = 0; ks < BK; ks += 16) {
            wmma::fragment<wmma::matrix_a, 16, 16, 16, __nv_bfloat16, wmma::row_major> ahf[2], alf[2];
            #pragma unroll
            for (int i2 = 0; i2 < 2; i2++) {
                wmma::load_matrix_sync(ahf[i2], Ah + (wm + i2 * 16) * LDSLD + ks, LDSLD);
                wmma::load_matrix_sync(alf[i2], Al + (wm + i2 * 16) * LDSLD + ks, LDSLD);
            }
            #pragma unroll
            for (int j = 0; j < 5; j++) {
                wmma::fragment<wmma::matrix_b, 16, 16, 16, __nv_bfloat16, wmma::col_major> bhf, blf;
                wmma::load_matrix_sync(bhf, Bh + (wn + j * 16) * LDSLD + ks, LDSLD);
                wmma::load_matrix_sync(blf, Bl + (wn + j * 16) * LDSLD + ks, LDSLD);
                #pragma unroll
                for (int i2 = 0; i2 < 2; i2++) {
                    wmma::mma_sync(acc[i2][j], ahf[i2], bhf, acc[i2][j]);   // hi*hi
                    wmma::mma_sync(acc[i2][j], ahf[i2], blf, acc[i2][j]);   // hi*lo
                    wmma::mma_sync(acc[i2][j], alf[i2], bhf, acc[i2][j]);   // lo*hi
                }
            }
        }
        if (i + 3 < NCHUNK) issue_stage(i + 3);
        cp_commit();           // unconditional: keeps wait_group bookkeeping exact
    }
    __syncthreads();           // all fragment loads done before smem reuse

    // ---- stage gates in smem ----------------------------------------------
    float* gates = (float*)sm;                 // [128][GLD]
    float* bsum  = (float*)(sm + BSUM_OFF);    // [160]
    #pragma unroll
    for (int i2 = 0; i2 < 2; i2++)
        #pragma unroll
        for (int j = 0; j < 5; j++)
            wmma::store_matrix_sync(gates + (wm + i2 * 16) * GLD + wn + j * 16, acc[i2][j],
                                    GLD, wmma::mem_row_major);
    if (tid < NG) {
        int g = tid >> 5, c = tid & 31;
        int gi = g * 1024 + h0 + c;
        bsum[tid] = bx[gi] + bh[gi];
    }
    __syncthreads();

    // ---- fused LSTM epilogue ----------------------------------------------
    #pragma unroll
    for (int p = 0; p < 16; p++) {
        int r = (tid >> 5) + p * 8;      // 0..127
        int c = tid & 31;                // 0..31
        size_t gidx = (size_t)(m0 + r) * 1024 + h0 + c;
        const float* gr = gates + r * GLD;

        float gi_ = gr[c]       + bsum[c];
        float gf_ = gr[32 + c]  + bsum[32 + c];
        float go_ = gr[64 + c]  + bsum[64 + c];
        float gc_ = gr[96 + c]  + bsum[96 + c];
        float gs_ = gr[128 + c] + bsum[128 + c];

        float i_t   = sigmoidf_fast(gi_);
        float f_t   = sigmoidf_fast(gf_);
        float o_t   = sigmoidf_fast(go_);
        float c_hat = tanhf(gc_);
        float s_t   = sigmoidf_fast(gs_) * dw[gidx];

        float c_t = f_t * c_prev[gidx] + i_t * c_hat * s_t;
        float h_t = o_t * tanhf(c_t);

        out[gidx] = h_t;
        out[(size_t)BATCH * HDIM + gidx] = c_t;
    }
}

// ---------------------------------------------------------------------------
// Inputs (metadata order): x, h_prev, c_prev, dynamic_weight, Wx, bx, Uh, bh
// ---------------------------------------------------------------------------
extern "C" void kernel_launch(void* const* d_in, const int* in_sizes, int n_in,
                              void* d_out, int out_size)
{
    const float* x  = (const float*)d_in[0];
    const float* hp = (const float*)d_in[1];
    const float* cp = (const float*)d_in[2];
    const float* dw = (const float*)d_in[3];
    const float* Wx = (const float*)d_in[4];
    const float* bx = (const float*)d_in[5];
    const float* Uh = (const float*)d_in[6];
    const float* bh = (const float*)d_in[7];
    float* out = (float*)d_out;

    const size_t total_units = (size_t)BATCH * KTOT / 8 + (size_t)WROWS * KTOT / 8;
    preprocess_kernel<<<(unsigned)((total_units + 255) / 256), 256>>>(x, hp, Wx, Uh);

    cudaFuncSetAttribute(lstm_mma_kernel,
                         cudaFuncAttributeMaxDynamicSharedMemorySize, SMEM_REQ);
    dim3 grid(HDIM / HB, BATCH / BM);   // (32, 128)
    lstm_mma_kernel<<<grid, 256, SMEM_REQ>>>(cp, dw, bx, bh, out);
}

// round 11
// speedup vs baseline: 5.6685x; 2.7571x over previous
#include <cuda_runtime.h>
#include <cuda_fp16.h>
#include <mma.h>
#include <cstdint>

using namespace nvcuda;

#define BATCH  16384
#define HDIM   1024
#define KTOT   2048
#define WROWS  5120          // 5 gates * 1024
#define BM     128           // batch rows per CTA
#define HB     64            // h columns per CTA
#define NG     320           // 5 gates * HB
#define BK     32            // K per chunk
#define NCHUNK (KTOT / BK)   // 64
#define LDSLD  40            // fp16 leading dim: 80B pitch, conflict-free LDSM
#define NSTAGE 4

// Stage layout (bytes): A [128][40] fp16 = 10240, B [320][40] fp16 = 25600
#define A_OFF 0
#define B_OFF 10240
#define STAGE 35840
#define GLD   324            // gates smem row stride (floats): 320 + 4 pad
#define BSUM_OFF (128 * GLD * 4)          // 165888
#define SMEM_REQ (BSUM_OFF + 1536)        // 167424 (also covers 4*STAGE=143360)

// Preprocessed fp16 operands (static device scratch, 84 MB)
__device__ __half g_Ah[(size_t)BATCH * KTOT];
__device__ __half g_Wh[(size_t)WROWS * KTOT];

__device__ __forceinline__ float sigmoidf_fast(float v) { return 1.0f / (1.0f + __expf(-v)); }
__device__ __forceinline__ uint32_t smem_u32(const void* p) {
    uint32_t a;
    asm("{ .reg .u64 t; cvta.to.shared.u64 t, %1; cvt.u32.u64 %0, t; }" : "=r"(a) : "l"(p));
    return a;
}
__device__ __forceinline__ void cpasync16(uint32_t dst, const void* src) {
    asm volatile("cp.async.cg.shared.global [%0], [%1], 16;" :: "r"(dst), "l"(src));
}
__device__ __forceinline__ void cp_commit() { asm volatile("cp.async.commit_group;" ::: "memory"); }
__device__ __forceinline__ void cp_wait2() { asm volatile("cp.async.wait_group 2;" ::: "memory"); }

// ---------------------------------------------------------------------------
// Preprocess: fp32 -> fp16.  A[16384][2048] = [x|h_prev], W[5120][2048] = [Wx|Uh]
// ---------------------------------------------------------------------------
__global__ __launch_bounds__(256)
void preprocess_kernel(const float* __restrict__ x, const float* __restrict__ h,
                       const float* __restrict__ Wx, const float* __restrict__ Uh)
{
    const size_t A_UNITS = (size_t)BATCH * KTOT / 8;   // 4194304
    const size_t W_UNITS = (size_t)WROWS * KTOT / 8;   // 1310720
    size_t u = (size_t)blockIdx.x * 256 + threadIdx.x;
    if (u >= A_UNITS + W_UNITS) return;

    const float* src;
    __half* dst;
    if (u < A_UNITS) {
        size_t row = u >> 8, col = (u & 255) * 8;
        src = (col < 1024) ? x + row * 1024 + col : h + row * 1024 + (col - 1024);
        dst = g_Ah + row * KTOT + col;
    } else {
        size_t v = u - A_UNITS;
        size_t row = v >> 8, col = (v & 255) * 8;
        src = (col < 1024) ? Wx + row * 1024 + col : Uh + row * 1024 + (col - 1024);
        dst = g_Wh + row * KTOT + col;
    }
    float4 f0 = *(const float4*)src;
    float4 f1 = *(const float4*)(src + 4);
    __half2 o[4];
    o[0] = __floats2half2_rn(f0.x, f0.y);
    o[1] = __floats2half2_rn(f0.z, f0.w);
    o[2] = __floats2half2_rn(f1.x, f1.y);
    o[3] = __floats2half2_rn(f1.z, f1.w);
    *(uint4*)dst = *(uint4*)o;
}

// ---------------------------------------------------------------------------
// GEMM (fp16 single-pass, fp32 acc) + fused LSTM epilogue.
// Warp grid 2(m) x 4(n); warp tile 64 x 80 -> acc[4][5].
// ---------------------------------------------------------------------------
__global__ __launch_bounds__(256, 1)
void lstm_mma_kernel(const float* __restrict__ c_prev, const float* __restrict__ dw,
                     const float* __restrict__ bx, const float* __restrict__ bh,
                     float* __restrict__ out)
{
    extern __shared__ char sm[];
    const int tid  = threadIdx.x;
    const int warp = tid >> 5;
    const int m0 = blockIdx.y * BM;
    const int h0 = blockIdx.x * HB;
    const uint32_t smb = smem_u32(sm);

    const int wm = (warp >> 2) * 64;    // 0 or 64
    const int wn = (warp & 3) * 80;     // 0,80,160,240

    wmma::fragment<wmma::accumulator, 16, 16, 16, float> acc[4][5];
    #pragma unroll
    for (int i = 0; i < 4; i++)
        #pragma unroll
        for (int j = 0; j < 5; j++) wmma::fill_fragment(acc[i][j], 0.0f);

    auto issue_stage = [&](int c) {
        const int kk = c * BK;
        const uint32_t base = smb + (c & (NSTAGE - 1)) * STAGE;
        #pragma unroll
        for (int p = 0; p < 2; p++) {               // A: 512 units of 16B
            int uu = tid + p * 256;
            int row = uu >> 2, seg = uu & 3;
            size_t go = (size_t)(m0 + row) * KTOT + kk + seg * 8;
            cpasync16(base + A_OFF + row * 80 + seg * 16, g_Ah + go);
        }
        #pragma unroll
        for (int p = 0; p < 5; p++) {               // B: 1280 units of 16B
            int uu = tid + p * 256;
            int row = uu >> 2, seg = uu & 3;        // row 0..319
            int wr = (row >> 6) * 1024 + h0 + (row & 63);
            size_t go = (size_t)wr * KTOT + kk + seg * 8;
            cpasync16(base + B_OFF + row * 80 + seg * 16, g_Wh + go);
        }
    };

    #pragma unroll
    for (int c = 0; c < 3; c++) { issue_stage(c); cp_commit(); }

    for (int i = 0; i < NCHUNK; i++) {
        cp_wait2();
        __syncthreads();

        const char* st = sm + (i & (NSTAGE - 1)) * STAGE;
        const __half* Ah = (const __half*)(st + A_OFF);
        const __half* Bh = (const __half*)(st + B_OFF);

        #pragma unroll
        for (int ks = 0; ks < BK; ks += 16) {
            wmma::fragment<wmma::matrix_a, 16, 16, 16, __half, wmma::row_major> ahf[4];
            #pragma unroll
            for (int i2 = 0; i2 < 4; i2++)
                wmma::load_matrix_sync(ahf[i2], Ah + (wm + i2 * 16) * LDSLD + ks, LDSLD);
            #pragma unroll
            for (int j = 0; j < 5; j++) {
                wmma::fragment<wmma::matrix_b, 16, 16, 16, __half, wmma::col_major> bhf;
                wmma::load_matrix_sync(bhf, Bh + (wn + j * 16) * LDSLD + ks, LDSLD);
                #pragma unroll
                for (int i2 = 0; i2 < 4; i2++)
                    wmma::mma_sync(acc[i2][j], ahf[i2], bhf, acc[i2][j]);
            }
        }
        if (i + 3 < NCHUNK) issue_stage(i + 3);
        cp_commit();
    }
    __syncthreads();

    // ---- stage gates in smem ----------------------------------------------
    float* gates = (float*)sm;                 // [128][GLD]
    float* bsum  = (float*)(sm + BSUM_OFF);    // [320]
    #pragma unroll
    for (int i2 = 0; i2 < 4; i2++)
        #pragma unroll
        for (int j = 0; j < 5; j++)
            wmma::store_matrix_sync(gates + (wm + i2 * 16) * GLD + wn + j * 16, acc[i2][j],
                                    GLD, wmma::mem_row_major);
    for (int i = tid; i < NG; i += 256) {
        int g = i >> 6, c = i & 63;
        int gi = g * 1024 + h0 + c;
        bsum[i] = bx[gi] + bh[gi];
    }
    __syncthreads();

    // ---- fused LSTM epilogue: 128*64 elems, 32/thread ----------------------
    #pragma unroll
    for (int p = 0; p < 32; p++) {
        int lin = p * 256 + tid;
        int r = lin >> 6;                // 0..127
        int c = lin & 63;                // 0..63
        size_t gidx = (size_t)(m0 + r) * 1024 + h0 + c;
        const float* gr = gates + r * GLD;

        float gi_ = gr[c]        + bsum[c];
        float gf_ = gr[64 + c]   + bsum[64 + c];
        float go_ = gr[128 + c]  + bsum[128 + c];
        float gc_ = gr[192 + c]  + bsum[192 + c];
        float gs_ = gr[256 + c]  + bsum[256 + c];

        float i_t   = sigmoidf_fast(gi_);
        float f_t   = sigmoidf_fast(gf_);
        float o_t   = sigmoidf_fast(go_);
        float c_hat = tanhf(gc_);
        float s_t   = sigmoidf_fast(gs_) * dw[gidx];

        float c_t = f_t * c_prev[gidx] + i_t * c_hat * s_t;
        float h_t = o_t * tanhf(c_t);

        out[gidx] = h_t;
        out[(size_t)BATCH * HDIM + gidx] = c_t;
    }
}

// ---------------------------------------------------------------------------
// Inputs (metadata order): x, h_prev, c_prev, dynamic_weight, Wx, bx, Uh, bh
// ---------------------------------------------------------------------------
extern "C" void kernel_launch(void* const* d_in, const int* in_sizes, int n_in,
                              void* d_out, int out_size)
{
    const float* x  = (const float*)d_in[0];
    const float* hp = (const float*)d_in[1];
    const float* cp = (const float*)d_in[2];
    const float* dw = (const float*)d_in[3];
    const float* Wx = (const float*)d_in[4];
    const float* bx = (const float*)d_in[5];
    const float* Uh = (const float*)d_in[6];
    const float* bh = (const float*)d_in[7];
    float* out = (float*)d_out;

    const size_t total_units = (size_t)BATCH * KTOT / 8 + (size_t)WROWS * KTOT / 8;
    preprocess_kernel<<<(unsigned)((total_units + 255) / 256), 256>>>(x, hp, Wx, Uh);

    cudaFuncSetAttribute(lstm_mma_kernel,
                         cudaFuncAttributeMaxDynamicSharedMemorySize, SMEM_REQ);
    dim3 grid(HDIM / HB, BATCH / BM);   // (16, 128)
    lstm_mma_kernel<<<grid, 256, SMEM_REQ>>>(cp, dw, bx, bh, out);
}